// round 1
// baseline (speedup 1.0000x reference)
#include <cuda_runtime.h>
#include <cuda_bf16.h>

// Problem constants (fixed shapes from reference):
//   Z: [2048, 32] f32, W1: [64, 64] f32 (row-major [2D][H]), b1: [64],
//   W2: [64, 1], b2: [1].  out: [2048, 2048] f32.
#define NN 2048
#define DD 32
#define HH 64

// Scratch for the factorized halves (allocation-free rule: __device__ globals).
__device__ float g_A[NN * HH];  // A[n][h] = Z[n]·W1[:D,h] + b1[h]
__device__ float g_B[NN * HH];  // B[n][h] = Z[n]·W1[D:,h]

// ---------------------------------------------------------------------------
// Packed f32x2 helpers (sm_100a: real ADD2/FFMA2 instructions, ptxas won't
// auto-fuse from C++ — must come from PTX f32x2 ops).
// ---------------------------------------------------------------------------
typedef unsigned long long u64t;

__device__ __forceinline__ u64t add_f32x2(u64t a, u64t b) {
    u64t d;
    asm("add.rn.f32x2 %0, %1, %2;" : "=l"(d) : "l"(a), "l"(b));
    return d;
}
__device__ __forceinline__ u64t fma_f32x2(u64t a, u64t b, u64t c) {
    u64t d;
    asm("fma.rn.f32x2 %0, %1, %2, %3;" : "=l"(d) : "l"(a), "l"(b), "l"(c));
    return d;
}
// relu on both halves; the mov.b64 pack/unpack collapses to register-pair
// aliasing in SASS (no extra MOVs when ptxas allocates the pair).
__device__ __forceinline__ u64t relu_f32x2(u64t t) {
    asm("{\n\t"
        ".reg .b32 lo, hi;\n\t"
        "mov.b64 {lo, hi}, %0;\n\t"
        "max.f32 lo, lo, 0f00000000;\n\t"
        "max.f32 hi, hi, 0f00000000;\n\t"
        "mov.b64 %0, {lo, hi};\n\t"
        "}" : "+l"(t));
    return t;
}

// ---------------------------------------------------------------------------
// Prep kernel: A[n][h] = sum_d Z[n,d]*W1[d,h] + b1[h];  B[n][h] = sum_d Z[n,d]*W1[D+d,h]
// 512 blocks x 256 threads, 4 rows per block. Tiny (~8 MFMA total).
// ---------------------------------------------------------------------------
__global__ void prep_kernel(const float* __restrict__ Z,
                            const float* __restrict__ W1,
                            const float* __restrict__ b1) {
    __shared__ float zs[4][DD];
    int tid = threadIdx.x;
    int nblk = blockIdx.x * 4;
    if (tid < 4 * DD) {
        zs[tid >> 5][tid & 31] = Z[(nblk + (tid >> 5)) * DD + (tid & 31)];
    }
    __syncthreads();
    int local_n = tid >> 6;        // 0..3
    int h = tid & 63;              // 0..63
    int n = nblk + local_n;
    float sa = b1[h];
    float sb = 0.0f;
#pragma unroll
    for (int d = 0; d < DD; d++) {
        float z = zs[local_n][d];
        sa = fmaf(z, W1[d * HH + h], sa);          // W1 reads coalesced in h, L1-hot
        sb = fmaf(z, W1[(DD + d) * HH + h], sb);
    }
    g_A[n * HH + h] = sa;
    g_B[n * HH + h] = sb;
}

// ---------------------------------------------------------------------------
// Main pair kernel. CTA tile 64(i) x 64(j), 256 threads, 4x4 pairs/thread with
// interleaved mapping i = ty + 16*ii, j = tx + 16*jj:
//   - B-row LDS.64: 16 distinct rows at padded word-stride 66 -> banks
//     (2*tx + h) cover all 32 banks exactly once: conflict-free.
//   - A-row LDS.64: 2 distinct addresses per warp (ty in {0,1}), distinct
//     banks: broadcast, conflict-free.
// Inner loop per 2 h-values per pair: ADD2 + 2xFMNMX + FFMA2 -> fma pipe at
// its 1-instr/pair-h floor; issue ~2.3 slots/pair-h is the binding limit.
// ---------------------------------------------------------------------------
#define SROW 66   // padded shared row stride in floats (264 B, 8B-aligned)

__global__ __launch_bounds__(256, 2)
void pair_kernel(const float* __restrict__ W2,
                 const float* __restrict__ b2,
                 float* __restrict__ out) {
    __shared__ float As[64 * SROW];
    __shared__ float Bs[64 * SROW];
    __shared__ float ws[HH];

    int tid = threadIdx.x;
    int bi = blockIdx.y * 64;
    int bj = blockIdx.x * 64;

    // Stage tiles (coalesced global reads, conflict-free shared writes).
    for (int idx = tid; idx < 64 * HH; idx += 256) {
        int r = idx >> 6;
        int h = idx & 63;
        As[r * SROW + h] = g_A[(bi + r) * HH + h];
        Bs[r * SROW + h] = g_B[(bj + r) * HH + h];
    }
    if (tid < HH) ws[tid] = W2[tid];
    __syncthreads();

    int tx = tid & 15;   // j lane
    int ty = tid >> 4;   // i lane

    u64t acc[4][4];
#pragma unroll
    for (int ii = 0; ii < 4; ii++)
#pragma unroll
        for (int jj = 0; jj < 4; jj++) acc[ii][jj] = 0ull;

    const float* arow0 = &As[ty * SROW];
    const float* brow0 = &Bs[tx * SROW];

#pragma unroll 4
    for (int h = 0; h < HH; h += 2) {
        u64t w2h = *(const u64t*)&ws[h];
        u64t a2[4], b2v[4];
#pragma unroll
        for (int ii = 0; ii < 4; ii++)
            a2[ii] = *(const u64t*)&arow0[ii * 16 * SROW + h];
#pragma unroll
        for (int jj = 0; jj < 4; jj++)
            b2v[jj] = *(const u64t*)&brow0[jj * 16 * SROW + h];
#pragma unroll
        for (int ii = 0; ii < 4; ii++) {
#pragma unroll
            for (int jj = 0; jj < 4; jj++) {
                u64t t = add_f32x2(a2[ii], b2v[jj]);
                t = relu_f32x2(t);
                acc[ii][jj] = fma_f32x2(t, w2h, acc[ii][jj]);
            }
        }
    }

    float bias = b2[0];
#pragma unroll
    for (int ii = 0; ii < 4; ii++) {
        int gi = bi + ty + ii * 16;
#pragma unroll
        for (int jj = 0; jj < 4; jj++) {
            int gj = bj + tx + jj * 16;
            float2 v = *(float2*)&acc[ii][jj];
            float x = v.x + v.y + bias;
            // sigmoid via fast exp + fast reciprocal (rel tol 1e-3 is generous)
            float e = __expf(-x);
            float s = __fdividef(1.0f, 1.0f + e);
            out[gi * NN + gj] = s;   // coalesced across tx
        }
    }
}

// ---------------------------------------------------------------------------
// Launch (graph-capturable: two plain kernel launches, no allocs/syncs).
// Input order per setup_inputs: Z, W1, b1, W2, b2.
// ---------------------------------------------------------------------------
extern "C" void kernel_launch(void* const* d_in, const int* in_sizes, int n_in,
                              void* d_out, int out_size) {
    const float* Z  = (const float*)d_in[0];
    const float* W1 = (const float*)d_in[1];
    const float* b1 = (const float*)d_in[2];
    const float* W2 = (const float*)d_in[3];
    const float* b2 = (const float*)d_in[4];
    float* out = (float*)d_out;

    prep_kernel<<<NN / 4, 256>>>(Z, W1, b1);
    dim3 grid(NN / 64, NN / 64);
    pair_kernel<<<grid, 256>>>(W2, b2, out);
}

// round 2
// speedup vs baseline: 1.0126x; 1.0126x over previous
#include <cuda_runtime.h>
#include <cuda_bf16.h>

// Shapes fixed by reference: Z[2048,32], W1[64,64], b1[64], W2[64,1], b2[1].
// out[i,j] = sigmoid( sum_h W2[h]*relu(A[i,h]+B[j,h]) + b2 )
//   with A = Z@W1[:D] + b1, B = Z@W1[D:].
// Identity used here: relu(a+b) = max(a,-b) + b, so
//   sum_h w*relu(a+b) = sum_h w*max(a,-b) + C_j,  C_j = sum_h w*B[j,h].
#define NN 2048
#define DD 32
#define HH 64

__device__ float g_A [NN * HH];  // A[n][h]
__device__ float g_nB[NN * HH];  // -B[n][h]  (negated so inner loop is pure max)
__device__ float g_C [NN];       // C[j] = sum_h W2[h]*B[j,h]

typedef unsigned long long u64t;

__device__ __forceinline__ u64t fma_f32x2(u64t a, u64t b, u64t c) {
    u64t d;
    asm("fma.rn.f32x2 %0, %1, %2, %3;" : "=l"(d) : "l"(a), "l"(b), "l"(c));
    return d;
}
// packed max via 2 scalar FMNMX (alu pipe); pack/unpack movs collapse to
// register-pair aliasing in SASS.
__device__ __forceinline__ u64t max2_f32(u64t a, u64t b) {
    u64t d;
    asm("{\n\t"
        ".reg .b32 al, ah, bl, bh, dl, dh;\n\t"
        "mov.b64 {al, ah}, %1;\n\t"
        "mov.b64 {bl, bh}, %2;\n\t"
        "max.f32 dl, al, bl;\n\t"
        "max.f32 dh, ah, bh;\n\t"
        "mov.b64 %0, {dl, dh};\n\t"
        "}" : "=l"(d) : "l"(a), "l"(b));
    return d;
}

// ---------------------------------------------------------------------------
// Prep: A, -B, and C. 512 blocks x 256 threads (4 rows/block). Tiny cost.
// ---------------------------------------------------------------------------
__global__ void prep_kernel(const float* __restrict__ Z,
                            const float* __restrict__ W1,
                            const float* __restrict__ b1,
                            const float* __restrict__ W2) {
    __shared__ float zs[4][DD];
    __shared__ float cbuf[4][HH];
    int tid = threadIdx.x;
    int nblk = blockIdx.x * 4;
    if (tid < 4 * DD) {
        zs[tid >> 5][tid & 31] = Z[(nblk + (tid >> 5)) * DD + (tid & 31)];
    }
    __syncthreads();
    int local_n = tid >> 6;        // 0..3
    int h = tid & 63;              // 0..63
    int n = nblk + local_n;
    float sa = b1[h];
    float sb = 0.0f;
#pragma unroll
    for (int d = 0; d < DD; d++) {
        float z = zs[local_n][d];
        sa = fmaf(z, W1[d * HH + h], sa);
        sb = fmaf(z, W1[(DD + d) * HH + h], sb);
    }
    g_A [n * HH + h] = sa;
    g_nB[n * HH + h] = -sb;
    cbuf[local_n][h] = sb * W2[h];
    __syncthreads();
    if (tid < 4) {
        float c = 0.0f;
#pragma unroll
        for (int k = 0; k < HH; k++) c += cbuf[tid][k];
        g_C[nblk + tid] = c;
    }
}

// ---------------------------------------------------------------------------
// Pair kernel: 64x64 tile, 256 threads, 4x4 pairs/thread, interleaved lanes
// (i = ty+16*ii, j = tx+16*jj) for conflict-free LDS.64.
// Inner loop per 2h per pair: 2x FMNMX (alu) + 1x FFMA2 (fma).
// ---------------------------------------------------------------------------
#define SROW 66   // padded shared row stride (floats)

__global__ __launch_bounds__(256, 3)
void pair_kernel(const float* __restrict__ W2,
                 const float* __restrict__ b2,
                 float* __restrict__ out) {
    __shared__ float As[64 * SROW];
    __shared__ float Bs[64 * SROW];   // holds -B
    __shared__ float ws[HH];
    __shared__ float Cs[64];

    int tid = threadIdx.x;
    int bi = blockIdx.y * 64;
    int bj = blockIdx.x * 64;

    for (int idx = tid; idx < 64 * HH; idx += 256) {
        int r = idx >> 6;
        int h = idx & 63;
        As[r * SROW + h] = g_A [(bi + r) * HH + h];
        Bs[r * SROW + h] = g_nB[(bj + r) * HH + h];
    }
    if (tid < HH) ws[tid] = W2[tid];
    if (tid >= 128 && tid < 192) Cs[tid - 128] = g_C[bj + (tid - 128)];
    __syncthreads();

    int tx = tid & 15;   // j lane
    int ty = tid >> 4;   // i lane

    u64t acc[4][4];
#pragma unroll
    for (int ii = 0; ii < 4; ii++)
#pragma unroll
        for (int jj = 0; jj < 4; jj++) acc[ii][jj] = 0ull;

    const float* arow0 = &As[ty * SROW];
    const float* brow0 = &Bs[tx * SROW];

#pragma unroll 4
    for (int h = 0; h < HH; h += 2) {
        u64t w2h = *(const u64t*)&ws[h];
        u64t a2[4], nb2[4];
#pragma unroll
        for (int ii = 0; ii < 4; ii++)
            a2[ii] = *(const u64t*)&arow0[ii * 16 * SROW + h];
#pragma unroll
        for (int jj = 0; jj < 4; jj++)
            nb2[jj] = *(const u64t*)&brow0[jj * 16 * SROW + h];
#pragma unroll
        for (int ii = 0; ii < 4; ii++) {
#pragma unroll
            for (int jj = 0; jj < 4; jj++) {
                u64t t = max2_f32(a2[ii], nb2[jj]);
                acc[ii][jj] = fma_f32x2(t, w2h, acc[ii][jj]);
            }
        }
    }

    float bias = b2[0];
#pragma unroll
    for (int ii = 0; ii < 4; ii++) {
        int gi = bi + ty + ii * 16;
#pragma unroll
        for (int jj = 0; jj < 4; jj++) {
            int gj = bj + tx + jj * 16;
            float2 v = *(float2*)&acc[ii][jj];
            float x = v.x + v.y + Cs[tx + jj * 16] + bias;
            float e = __expf(-x);
            float s = __fdividef(1.0f, 1.0f + e);
            out[gi * NN + gj] = s;   // coalesced across tx
        }
    }
}

extern "C" void kernel_launch(void* const* d_in, const int* in_sizes, int n_in,
                              void* d_out, int out_size) {
    const float* Z  = (const float*)d_in[0];
    const float* W1 = (const float*)d_in[1];
    const float* b1 = (const float*)d_in[2];
    const float* W2 = (const float*)d_in[3];
    const float* b2 = (const float*)d_in[4];
    float* out = (float*)d_out;

    prep_kernel<<<NN / 4, 256>>>(Z, W1, b1, W2);
    dim3 grid(NN / 64, NN / 64);
    pair_kernel<<<grid, 256>>>(W2, b2, out);
}

// round 3
// speedup vs baseline: 1.0633x; 1.0500x over previous
#include <cuda_runtime.h>
#include <cuda_bf16.h>

// Shapes fixed by reference: Z[2048,32], W1[64,64], b1[64], W2[64,1], b2[1].
// out[i,j] = sigmoid( sum_h W2[h]*relu(A[i,h]+B[j,h]) + b2 )
//   with A = Z@W1[:D] + b1, B = Z@W1[D:].
// Identity: relu(a+b) = max(a,-b) + b  =>
//   sum_h w*relu(a+b) = sum_h w*max(a,-b) + C_j,  C_j = sum_h w*B[j,h].
#define NN 2048
#define DD 32
#define HH 64

__device__ float g_A [NN * HH];  // A[n][h]
__device__ float g_nB[NN * HH];  // -B[n][h]
__device__ float g_C [NN];       // C[j] = sum_h W2[h]*B[j,h]

typedef unsigned long long u64t;

__device__ __forceinline__ u64t fma_f32x2(u64t a, u64t b, u64t c) {
    u64t d;
    asm("fma.rn.f32x2 %0, %1, %2, %3;" : "=l"(d) : "l"(a), "l"(b), "l"(c));
    return d;
}
// packed max via 2 scalar FMNMX (alu pipe); movs collapse to reg-pair aliasing.
__device__ __forceinline__ u64t max2_f32(u64t a, u64t b) {
    u64t d;
    asm("{\n\t"
        ".reg .b32 al, ah, bl, bh, dl, dh;\n\t"
        "mov.b64 {al, ah}, %1;\n\t"
        "mov.b64 {bl, bh}, %2;\n\t"
        "max.f32 dl, al, bl;\n\t"
        "max.f32 dh, ah, bh;\n\t"
        "mov.b64 %0, {dl, dh};\n\t"
        "}" : "=l"(d) : "l"(a), "l"(b));
    return d;
}

// ---------------------------------------------------------------------------
// Prep: A, -B, and C. 512 blocks x 256 threads (4 rows/block). Tiny cost.
// ---------------------------------------------------------------------------
__global__ void prep_kernel(const float* __restrict__ Z,
                            const float* __restrict__ W1,
                            const float* __restrict__ b1,
                            const float* __restrict__ W2) {
    __shared__ float zs[4][DD];
    __shared__ float cbuf[4][HH];
    int tid = threadIdx.x;
    int nblk = blockIdx.x * 4;
    if (tid < 4 * DD) {
        zs[tid >> 5][tid & 31] = Z[(nblk + (tid >> 5)) * DD + (tid & 31)];
    }
    __syncthreads();
    int local_n = tid >> 6;        // 0..3
    int h = tid & 63;              // 0..63
    int n = nblk + local_n;
    float sa = b1[h];
    float sb = 0.0f;
#pragma unroll
    for (int d = 0; d < DD; d++) {
        float z = zs[local_n][d];
        sa = fmaf(z, W1[d * HH + h], sa);
        sb = fmaf(z, W1[(DD + d) * HH + h], sb);
    }
    g_A [n * HH + h] = sa;
    g_nB[n * HH + h] = -sb;
    cbuf[local_n][h] = sb * W2[h];
    __syncthreads();
    if (tid < 4) {
        float c = 0.0f;
#pragma unroll
        for (int k = 0; k < HH; k++) c += cbuf[tid][k];
        g_C[nblk + tid] = c;
    }
}

// ---------------------------------------------------------------------------
// Pair kernel: 64x64 tile, 256 threads, 4x4 pairs/thread, interleaved lanes
// (i = ty+16*ii, j = tx+16*jj) for conflict-free LDS.64 (SROW=66 => banks
// 2*tx+h cover all 32 banks exactly once).
// Inner loop per 2h per pair: 2x FMNMX (alu) + 1x FFMA2 (fma).
// launch_bounds(256,4): cap at 64 regs so 4 CTAs/SM (32 warps) fit; the jj
// loop loads B operands at point-of-use to keep the live set ~52 regs.
// ---------------------------------------------------------------------------
#define SROW 66   // padded shared row stride (floats)

__global__ __launch_bounds__(256, 4)
void pair_kernel(const float* __restrict__ W2,
                 const float* __restrict__ b2,
                 float* __restrict__ out) {
    __shared__ float As[64 * SROW];
    __shared__ float Bs[64 * SROW];   // holds -B
    __shared__ float ws[HH];
    __shared__ float Cs[64];

    int tid = threadIdx.x;
    int bi = blockIdx.y * 64;
    int bj = blockIdx.x * 64;

    for (int idx = tid; idx < 64 * HH; idx += 256) {
        int r = idx >> 6;
        int h = idx & 63;
        As[r * SROW + h] = g_A [(bi + r) * HH + h];
        Bs[r * SROW + h] = g_nB[(bj + r) * HH + h];
    }
    if (tid < HH) ws[tid] = W2[tid];
    if (tid >= 128 && tid < 192) Cs[tid - 128] = g_C[bj + (tid - 128)];
    __syncthreads();

    int tx = tid & 15;   // j lane
    int ty = tid >> 4;   // i lane

    u64t acc[4][4];
#pragma unroll
    for (int ii = 0; ii < 4; ii++)
#pragma unroll
        for (int jj = 0; jj < 4; jj++) acc[ii][jj] = 0ull;

    const float* arow0 = &As[ty * SROW];
    const float* brow0 = &Bs[tx * SROW];

#pragma unroll 4
    for (int h = 0; h < HH; h += 2) {
        u64t w2h = *(const u64t*)&ws[h];
        u64t a2[4];
#pragma unroll
        for (int ii = 0; ii < 4; ii++)
            a2[ii] = *(const u64t*)&arow0[ii * 16 * SROW + h];
#pragma unroll
        for (int jj = 0; jj < 4; jj++) {
            u64t nb = *(const u64t*)&brow0[jj * 16 * SROW + h];
#pragma unroll
            for (int ii = 0; ii < 4; ii++) {
                u64t t = max2_f32(a2[ii], nb);
                acc[ii][jj] = fma_f32x2(t, w2h, acc[ii][jj]);
            }
        }
    }

    float bias = b2[0];
#pragma unroll
    for (int ii = 0; ii < 4; ii++) {
        int gi = bi + ty + ii * 16;
#pragma unroll
        for (int jj = 0; jj < 4; jj++) {
            int gj = bj + tx + jj * 16;
            float2 v = *(float2*)&acc[ii][jj];
            float x = v.x + v.y + Cs[tx + jj * 16] + bias;
            float e = __expf(-x);
            float s = __fdividef(1.0f, 1.0f + e);
            out[gi * NN + gj] = s;   // coalesced across tx
        }
    }
}

extern "C" void kernel_launch(void* const* d_in, const int* in_sizes, int n_in,
                              void* d_out, int out_size) {
    const float* Z  = (const float*)d_in[0];
    const float* W1 = (const float*)d_in[1];
    const float* b1 = (const float*)d_in[2];
    const float* W2 = (const float*)d_in[3];
    const float* b2 = (const float*)d_in[4];
    float* out = (float*)d_out;

    prep_kernel<<<NN / 4, 256>>>(Z, W1, b1, W2);
    dim3 grid(NN / 64, NN / 64);
    pair_kernel<<<grid, 256>>>(W2, b2, out);
}